// round 2
// baseline (speedup 1.0000x reference)
#include <cuda_runtime.h>
#include <cstdint>

#define BB 2
#define TT 4096
#define CC 2048
#define HH 32
#define NT (BB*TT)   // 8192 tokens

typedef unsigned long long ull;

// ---------------- scratch (static device arrays; no allocations) ----------------
__device__ float g_r [NT*CC];
__device__ float g_k [NT*CC];
__device__ float g_v [NT*CC];
__device__ float g_xw[NT*CC];
__device__ float g_wd[NT*CC];

// ---------------- packed f32x2 helpers ----------------
__device__ __forceinline__ ull pk(float lo, float hi){
    ull r; asm("mov.b64 %0,{%1,%2};" : "=l"(r) : "f"(lo), "f"(hi)); return r;
}
__device__ __forceinline__ ull dup(float x){
    ull r; asm("mov.b64 %0,{%1,%1};" : "=l"(r) : "f"(x)); return r;
}
__device__ __forceinline__ float2 up2(ull a){
    float2 f; asm("mov.b64 {%0,%1},%2;" : "=f"(f.x), "=f"(f.y) : "l"(a)); return f;
}
__device__ __forceinline__ ull fma2(ull a, ull b, ull c){
    ull d; asm("fma.rn.f32x2 %0,%1,%2,%3;" : "=l"(d) : "l"(a), "l"(b), "l"(c)); return d;
}
__device__ __forceinline__ ull mul2(ull a, ull b){
    ull d; asm("mul.rn.f32x2 %0,%1,%2;" : "=l"(d) : "l"(a), "l"(b)); return d;
}
__device__ __forceinline__ void cpa4(uint32_t dst, const void* src){
    asm volatile("cp.async.ca.shared.global [%0],[%1],4;\n" :: "r"(dst), "l"(src) : "memory");
}
__device__ __forceinline__ void cpa_commit(){
    asm volatile("cp.async.commit_group;\n" ::: "memory");
}

// =====================================================================
// Kernel 1: token-shift mix. Block = 64 tokens, 256 threads, grid = 128.
//   Phase A: xxx = tanh(z @ W1[:, :128]), z = x + (prev - x)*maa_x
//   Phase B: m_f = xxx_f @ W2[f]; xf = x + xx*(maa_f + m_f), f in {w,k,v,r}
// =====================================================================
__global__ __launch_bounds__(256) void k_mix(
    const float* __restrict__ hidden, const float* __restrict__ attn_x,
    const float* __restrict__ maa_x,  const float* __restrict__ maa_w,
    const float* __restrict__ maa_k,  const float* __restrict__ maa_v,
    const float* __restrict__ maa_r,  const float* __restrict__ w1,
    const float* __restrict__ w2)
{
    extern __shared__ float sm[];
    float* xxx_s = sm;                  // [64][128]  (persistent)
    float* As    = sm + 64*128;         // [32][68]   (phase A)
    float* Bs    = As + 32*68;          // [32][128]  (phase A)
    float* w2_s  = sm + 64*128;         // [128][128] (phase B, overlaps As/Bs)

    const int tid = threadIdx.x;
    const int tx = tid & 15, ty = tid >> 4;
    const int bt0 = blockIdx.x * 64;

    // ---------------- Phase A: GEMM1 (64 x 128, K=2048) ----------------
    ull acc[4][4];
    #pragma unroll
    for (int i = 0; i < 4; i++)
        #pragma unroll
        for (int j = 0; j < 4; j++) acc[i][j] = 0ull;

    for (int kc = 0; kc < CC; kc += 32){
        #pragma unroll
        for (int l = 0; l < 8; l++){
            int i  = tid + l*256;
            int tl = i >> 5, kk = i & 31;
            int tok = bt0 + tl;
            int c = kc + kk;
            float x = hidden[(size_t)tok*CC + c];
            float p = ((tok & (TT-1)) == 0) ? attn_x[(size_t)(tok >> 12)*CC + c]
                                            : hidden[(size_t)(tok-1)*CC + c];
            As[kk*68 + tl] = x + (p - x)*maa_x[c];
        }
        #pragma unroll
        for (int l = 0; l < 16; l++){
            int i  = tid + l*256;
            int kk = i >> 7, n = i & 127;
            Bs[kk*128 + n] = w1[(size_t)(kc+kk)*160 + n];
        }
        __syncthreads();
        #pragma unroll
        for (int kk = 0; kk < 32; kk++){
            float4 av = *(const float4*)&As[kk*68 + ty*4];
            ulonglong2 b01 = *(const ulonglong2*)&Bs[kk*128 + tx*8];
            ulonglong2 b23 = *(const ulonglong2*)&Bs[kk*128 + tx*8 + 4];
            ull bp[4] = {b01.x, b01.y, b23.x, b23.y};
            float aa[4] = {av.x, av.y, av.z, av.w};
            #pragma unroll
            for (int i = 0; i < 4; i++){
                ull ad = dup(aa[i]);
                #pragma unroll
                for (int j = 0; j < 4; j++) acc[i][j] = fma2(ad, bp[j], acc[i][j]);
            }
        }
        __syncthreads();
    }
    #pragma unroll
    for (int i = 0; i < 4; i++){
        #pragma unroll
        for (int jp = 0; jp < 4; jp++){
            float2 f = up2(acc[i][jp]);
            int r = (ty*4 + i)*128 + tx*8 + 2*jp;
            xxx_s[r]   = tanhf(f.x);
            xxx_s[r+1] = tanhf(f.y);
        }
    }
    __syncthreads();

    // ---------------- Phase B: 4x rank-32 + epilogue ----------------
    for (int c0 = 0; c0 < CC; c0 += 128){
        #pragma unroll
        for (int l = 0; l < 64; l++){
            int i = tid + l*256;
            w2_s[i] = w2[(size_t)(i >> 7)*CC + c0 + (i & 127)];
        }
        __syncthreads();

        #pragma unroll
        for (int it = 0; it < 4; it++){
            const int tl  = ty*4 + it;
            const int tok = bt0 + tl;
            ull m2[4][4];
            #pragma unroll
            for (int f = 0; f < 4; f++)
                #pragma unroll
                for (int j = 0; j < 4; j++) m2[f][j] = 0ull;

            #pragma unroll
            for (int kk = 0; kk < 32; kk++){
                #pragma unroll
                for (int f = 0; f < 4; f++){
                    ull ad = dup(xxx_s[tl*128 + f*32 + kk]);
                    ulonglong2 wa = *(const ulonglong2*)&w2_s[(f*32+kk)*128 + tx*8];
                    ulonglong2 wb = *(const ulonglong2*)&w2_s[(f*32+kk)*128 + tx*8 + 4];
                    m2[f][0] = fma2(ad, wa.x, m2[f][0]);
                    m2[f][1] = fma2(ad, wa.y, m2[f][1]);
                    m2[f][2] = fma2(ad, wb.x, m2[f][2]);
                    m2[f][3] = fma2(ad, wb.y, m2[f][3]);
                }
            }
            // epilogue
            const int cb = c0 + tx*8;
            const size_t gofs = (size_t)tok*CC + cb;
            float4 xa = *(const float4*)&hidden[gofs];
            float4 xb = *(const float4*)&hidden[gofs + 4];
            const float* prow = ((tok & (TT-1)) == 0) ? (attn_x + (size_t)(tok >> 12)*CC)
                                                      : (hidden + (size_t)(tok-1)*CC);
            float4 pa = *(const float4*)&prow[cb];
            float4 pb = *(const float4*)&prow[cb + 4];
            float xv[8] = {xa.x,xa.y,xa.z,xa.w,xb.x,xb.y,xb.z,xb.w};
            float pv[8] = {pa.x,pa.y,pa.z,pa.w,pb.x,pb.y,pb.z,pb.w};
            float xd[8];
            #pragma unroll
            for (int e = 0; e < 8; e++) xd[e] = pv[e] - xv[e];

            float* gouts[4]       = {g_xw, g_k, g_v, g_r};
            const float* maas[4]  = {maa_w, maa_k, maa_v, maa_r};
            #pragma unroll
            for (int f = 0; f < 4; f++){
                float4 ma = *(const float4*)&maas[f][cb];
                float4 mb = *(const float4*)&maas[f][cb + 4];
                float mm[8] = {ma.x,ma.y,ma.z,ma.w,mb.x,mb.y,mb.z,mb.w};
                float mq[8];
                #pragma unroll
                for (int jp = 0; jp < 4; jp++){
                    float2 qv = up2(m2[f][jp]);
                    mq[2*jp] = qv.x; mq[2*jp+1] = qv.y;
                }
                float o[8];
                #pragma unroll
                for (int e = 0; e < 8; e++) o[e] = xv[e] + xd[e]*(mm[e] + mq[e]);
                *(float4*)&gouts[f][gofs]     = make_float4(o[0],o[1],o[2],o[3]);
                *(float4*)&gouts[f][gofs + 4] = make_float4(o[4],o[5],o[6],o[7]);
            }
        }
        __syncthreads();
    }
}

// =====================================================================
// Kernel 2: decay LoRA. Block = 64 tokens, 256 threads, grid = 128.
//   d1 = tanh(xw @ dw1);  wd = exp(-exp(time_decay + d1 @ dw2))
// =====================================================================
__global__ __launch_bounds__(256) void k_decay(
    const float* __restrict__ dw1, const float* __restrict__ dw2,
    const float* __restrict__ tdecay)
{
    extern __shared__ float sm[];
    float* d1_s  = sm;                 // [64][68] (persistent)
    float* As    = sm + 64*68;         // [32][68]
    float* Bs    = As + 32*68;         // [32][64]
    float* dw2_s = sm + 64*68;         // [64][128] (phase B, overlaps)

    const int tid = threadIdx.x;
    const int tx = tid & 15, ty = tid >> 4;
    const int bt0 = blockIdx.x * 64;

    ull acc[4][2];
    #pragma unroll
    for (int i = 0; i < 4; i++){ acc[i][0] = 0ull; acc[i][1] = 0ull; }

    for (int kc = 0; kc < CC; kc += 32){
        #pragma unroll
        for (int l = 0; l < 8; l++){
            int i  = tid + l*256;
            int tl = i >> 5, kk = i & 31;
            As[kk*68 + tl] = g_xw[(size_t)(bt0 + tl)*CC + kc + kk];
        }
        #pragma unroll
        for (int l = 0; l < 8; l++){
            int i  = tid + l*256;
            int kk = i >> 6, j = i & 63;
            Bs[kk*64 + j] = dw1[(size_t)(kc+kk)*64 + j];
        }
        __syncthreads();
        #pragma unroll
        for (int kk = 0; kk < 32; kk++){
            float4 av = *(const float4*)&As[kk*68 + ty*4];
            ulonglong2 bb = *(const ulonglong2*)&Bs[kk*64 + tx*4];
            float aa[4] = {av.x, av.y, av.z, av.w};
            #pragma unroll
            for (int i = 0; i < 4; i++){
                ull ad = dup(aa[i]);
                acc[i][0] = fma2(ad, bb.x, acc[i][0]);
                acc[i][1] = fma2(ad, bb.y, acc[i][1]);
            }
        }
        __syncthreads();
    }
    #pragma unroll
    for (int i = 0; i < 4; i++){
        float2 e0 = up2(acc[i][0]);
        float2 e1 = up2(acc[i][1]);
        int r = (ty*4 + i)*68 + tx*4;
        d1_s[r]   = tanhf(e0.x);
        d1_s[r+1] = tanhf(e0.y);
        d1_s[r+2] = tanhf(e1.x);
        d1_s[r+3] = tanhf(e1.y);
    }
    __syncthreads();

    for (int c0 = 0; c0 < CC; c0 += 128){
        #pragma unroll
        for (int l = 0; l < 32; l++){
            int i = tid + l*256;
            dw2_s[i] = dw2[(size_t)(i >> 7)*CC + c0 + (i & 127)];
        }
        __syncthreads();
        #pragma unroll
        for (int it = 0; it < 4; it++){
            const int tl  = ty*4 + it;
            const int tok = bt0 + tl;
            ull a2[4];
            #pragma unroll
            for (int j = 0; j < 4; j++) a2[j] = 0ull;
            #pragma unroll
            for (int jj = 0; jj < 64; jj++){
                ull ad = dup(d1_s[tl*68 + jj]);
                ulonglong2 wa = *(const ulonglong2*)&dw2_s[jj*128 + tx*8];
                ulonglong2 wb = *(const ulonglong2*)&dw2_s[jj*128 + tx*8 + 4];
                a2[0] = fma2(ad, wa.x, a2[0]);
                a2[1] = fma2(ad, wa.y, a2[1]);
                a2[2] = fma2(ad, wb.x, a2[2]);
                a2[3] = fma2(ad, wb.y, a2[3]);
            }
            const int cb = c0 + tx*8;
            float4 t0 = *(const float4*)&tdecay[cb];
            float4 t1 = *(const float4*)&tdecay[cb + 4];
            float td[8] = {t0.x,t0.y,t0.z,t0.w,t1.x,t1.y,t1.z,t1.w};
            float mq[8];
            #pragma unroll
            for (int jp = 0; jp < 4; jp++){
                float2 qv = up2(a2[jp]);
                mq[2*jp] = qv.x; mq[2*jp+1] = qv.y;
            }
            float o[8];
            #pragma unroll
            for (int e = 0; e < 8; e++) o[e] = expf(-expf(td[e] + mq[e]));
            size_t gofs = (size_t)tok*CC + cb;
            *(float4*)&g_wd[gofs]     = make_float4(o[0],o[1],o[2],o[3]);
            *(float4*)&g_wd[gofs + 4] = make_float4(o[4],o[5],o[6],o[7]);
        }
        __syncthreads();
    }
}

// =====================================================================
// Kernel 3: WKV scan. One block per (b,h). 256 threads:
//   m = tid&63 (output dim), q = tid>>6 (n-quarter). 8 f32x2 state pairs
//   per thread packed along n. cp.async ring of 8 stages, 4 steps/group.
// =====================================================================
__global__ __launch_bounds__(256) void k_scan(
    const float* __restrict__ attn_kv, const float* __restrict__ faaaa,
    float* __restrict__ out)
{
    __shared__ float stage[8][256];    // [stage][a*64+e], a: 0=r,1=k,2=w,3=v
    __shared__ float partial[4][256];

    const int tid = threadIdx.x;
    const int bh = blockIdx.x;
    const int b = bh >> 5, h = bh & 31;
    const int m = tid & 63, q = tid >> 6;

    const ull ud = dup(faaaa[h]);

    // init state pairs: s2[j] = (S[n0][m], S[n0+1][m]), n0 = q*16+2j
    ull s2[8];
    const float* kvp = attn_kv + (size_t)(b*HH + h)*64*64;
    #pragma unroll
    for (int j = 0; j < 8; j++){
        int n0 = q*16 + 2*j;
        s2[j] = pk(kvp[n0*64 + m], kvp[(n0+1)*64 + m]);
    }

    // this thread's global source: array q, element m, per step t
    const float* src;
    if      (q == 0) src = g_r;
    else if (q == 1) src = g_k;
    else if (q == 2) src = g_wd;
    else             src = g_v;
    src += (size_t)b*TT*CC + h*64 + m;

    const uint32_t sbase = (uint32_t)__cvta_generic_to_shared(&stage[0][0]);
    float* outp = out + (size_t)b*TT*CC + h*64;

    // prologue: groups 0 and 1 (steps 0..7)
    #pragma unroll
    for (int t = 0; t < 4; t++) cpa4(sbase + (uint32_t)((t&7)*256 + tid)*4u, src + (size_t)t*CC);
    cpa_commit();
    #pragma unroll
    for (int t = 4; t < 8; t++) cpa4(sbase + (uint32_t)((t&7)*256 + tid)*4u, src + (size_t)t*CC);
    cpa_commit();

    for (int g = 0; g < TT/4; g++){
        asm volatile("cp.async.wait_group 1;\n" ::: "memory");
        __syncthreads();
        #pragma unroll
        for (int ti = 0; ti < 4; ti++){
            const int t = g*4 + ti;
            const float* st = stage[t & 7];
            const ull vd = dup(st[192 + m]);
            ull y2a = 0ull, y2b = 0ull;
            #pragma unroll
            for (int j = 0; j < 8; j++){
                const int n0 = q*16 + 2*j;
                ull r2  = *(const ull*)&st[n0];
                ull k2  = *(const ull*)&st[64 + n0];
                ull w2v = *(const ull*)&st[128 + n0];
                ull a2  = mul2(k2, vd);
                ull t2  = fma2(ud, a2, s2[j]);        // s + u*a
                if (j & 1) y2b = fma2(r2, t2, y2b);
                else       y2a = fma2(r2, t2, y2a);
                s2[j] = fma2(w2v, s2[j], a2);
            }
            float2 fa = up2(y2a), fb = up2(y2b);
            partial[ti][tid] = (fa.x + fa.y) + (fb.x + fb.y);
        }
        __syncthreads();
        // reduction + store: thread tid -> step q, output dim m
        {
            float y = partial[q][m] + partial[q][64 + m]
                    + partial[q][128 + m] + partial[q][192 + m];
            outp[(size_t)(g*4 + q)*CC + m] = y;
        }
        // issue group g+2 into the slots just consumed
        if (g + 2 < TT/4){
            const int tb = (g + 2)*4;
            #pragma unroll
            for (int ti2 = 0; ti2 < 4; ti2++){
                const int t = tb + ti2;
                cpa4(sbase + (uint32_t)((t&7)*256 + tid)*4u, src + (size_t)t*CC);
            }
        }
        cpa_commit();
    }
}

// =====================================================================
extern "C" void kernel_launch(void* const* d_in, const int* in_sizes, int n_in,
                              void* d_out, int out_size) {
    const float* hidden  = (const float*)d_in[0];
    const float* attn_x  = (const float*)d_in[1];
    const float* attn_kv = (const float*)d_in[2];
    // d_in[3] = ffn_x (unused)
    const float* maa_x   = (const float*)d_in[4];
    const float* maa_w   = (const float*)d_in[5];
    const float* maa_k   = (const float*)d_in[6];
    const float* maa_v   = (const float*)d_in[7];
    const float* maa_r   = (const float*)d_in[8];
    // d_in[9] = time_maa_g (unused)
    const float* w1      = (const float*)d_in[10];
    const float* w2      = (const float*)d_in[11];
    const float* tdecay  = (const float*)d_in[12];
    const float* dw1     = (const float*)d_in[13];
    const float* dw2     = (const float*)d_in[14];
    const float* faaaa   = (const float*)d_in[15];
    float* out = (float*)d_out;

    static bool attr_set = false;
    if (!attr_set){
        cudaFuncSetAttribute(k_mix,   cudaFuncAttributeMaxDynamicSharedMemorySize, 98304);
        cudaFuncSetAttribute(k_decay, cudaFuncAttributeMaxDynamicSharedMemorySize, 50176);
        attr_set = true;
    }

    k_mix  <<<NT/64, 256, 98304>>>(hidden, attn_x, maa_x, maa_w, maa_k, maa_v, maa_r, w1, w2);
    k_decay<<<NT/64, 256, 50176>>>(dw1, dw2, tdecay);
    k_scan <<<BB*HH, 256>>>(attn_kv, faaaa, out);
}

// round 3
// speedup vs baseline: 1.2928x; 1.2928x over previous
#include <cuda_runtime.h>
#include <cstdint>

#define BB 2
#define TT 4096
#define CC 2048
#define NT (BB*TT)   // 8192 tokens

typedef unsigned long long ull;

// interleaved scan input: [tok][h][f][64], f: 0=r, 1=k, 2=wd, 3=v  (256MB)
__device__ float g_seq[(size_t)NT*32*4*64];

// ---------------- packed f32x2 helpers ----------------
__device__ __forceinline__ ull pk(float lo, float hi){
    ull r; asm("mov.b64 %0,{%1,%2};" : "=l"(r) : "f"(lo), "f"(hi)); return r;
}
__device__ __forceinline__ ull dup(float x){
    ull r; asm("mov.b64 %0,{%1,%1};" : "=l"(r) : "f"(x)); return r;
}
__device__ __forceinline__ float2 up2(ull a){
    float2 f; asm("mov.b64 {%0,%1},%2;" : "=f"(f.x), "=f"(f.y) : "l"(a)); return f;
}
__device__ __forceinline__ ull fma2(ull a, ull b, ull c){
    ull d; asm("fma.rn.f32x2 %0,%1,%2,%3;" : "=l"(d) : "l"(a), "l"(b), "l"(c)); return d;
}
__device__ __forceinline__ ull mul2(ull a, ull b){
    ull d; asm("mul.rn.f32x2 %0,%1,%2;" : "=l"(d) : "l"(a), "l"(b)); return d;
}
__device__ __forceinline__ void cpa16(uint32_t dst, const void* src){
    asm volatile("cp.async.cg.shared.global [%0],[%1],16;\n" :: "r"(dst), "l"(src) : "memory");
}
__device__ __forceinline__ void cpa_commit(){
    asm volatile("cp.async.commit_group;\n" ::: "memory");
}

// shared-memory layout for k_fused (float offsets)
#define OFF_XXX 0            // [64][128]   8192
#define OFF_A   8192         // [32][68]    2176   (phase A)
#define OFF_B   (8192+2176)  // [32][128]   4096   (phase A)
#define OFF_W2  8192         // [128][128] 16384   (phase B)
#define OFF_DW1 24576        // [128][68]   8704   (phase B)
#define OFF_XW  33280        // [64][132]   8448   (phase B)
#define OFF_D1  8192         // [64][68]    4352   (phase C)
#define OFF_DW2 12544        // [64][128]   8192   (phase C)
#define SMEM_FUSED_BYTES (41728*4)

// =====================================================================
// k_fused: token-shift mix + decay LoRA. Block = 64 tokens, 256 thr.
//  A: xxx = tanh(z @ W1[:, :128])
//  B: per 128-col chunk: m_f = xxx_f @ W2[f]; xf epilogue; write k,v,r
//     to g_seq; keep xw in smem; accumulate d1 += xw_chunk @ dw1_chunk.
//  C: wd = exp(-exp(td + tanh(d1) @ dw2)) -> g_seq slot 2.
// =====================================================================
__global__ __launch_bounds__(256) void k_fused(
    const float* __restrict__ hidden, const float* __restrict__ attn_x,
    const float* __restrict__ maa_x,  const float* __restrict__ maa_w,
    const float* __restrict__ maa_k,  const float* __restrict__ maa_v,
    const float* __restrict__ maa_r,  const float* __restrict__ w1,
    const float* __restrict__ w2,     const float* __restrict__ dw1,
    const float* __restrict__ dw2,    const float* __restrict__ tdecay)
{
    extern __shared__ float sm[];
    const int tid = threadIdx.x;
    const int tx = tid & 15, ty = tid >> 4;
    const int bt0 = blockIdx.x * 64;

    // ---------------- Phase A: GEMM1 (64 x 128, K=2048) ----------------
    {
        float* As = sm + OFF_A;
        float* Bs = sm + OFF_B;
        ull acc[4][4];
        #pragma unroll
        for (int i = 0; i < 4; i++)
            #pragma unroll
            for (int j = 0; j < 4; j++) acc[i][j] = 0ull;

        for (int kc = 0; kc < CC; kc += 32){
            #pragma unroll
            for (int l = 0; l < 8; l++){
                int i  = tid + l*256;
                int tl = i >> 5, kk = i & 31;
                int tok = bt0 + tl;
                int c = kc + kk;
                float x = hidden[(size_t)tok*CC + c];
                float p = ((tok & (TT-1)) == 0) ? attn_x[(size_t)(tok >> 12)*CC + c]
                                                : hidden[(size_t)(tok-1)*CC + c];
                As[kk*68 + tl] = x + (p - x)*maa_x[c];
            }
            #pragma unroll
            for (int l = 0; l < 16; l++){
                int i  = tid + l*256;
                int kk = i >> 7, n = i & 127;
                Bs[kk*128 + n] = w1[(size_t)(kc+kk)*160 + n];
            }
            __syncthreads();
            #pragma unroll
            for (int kk = 0; kk < 32; kk++){
                float4 av = *(const float4*)&As[kk*68 + ty*4];
                ulonglong2 b01 = *(const ulonglong2*)&Bs[kk*128 + tx*8];
                ulonglong2 b23 = *(const ulonglong2*)&Bs[kk*128 + tx*8 + 4];
                ull bp[4] = {b01.x, b01.y, b23.x, b23.y};
                float aa[4] = {av.x, av.y, av.z, av.w};
                #pragma unroll
                for (int i = 0; i < 4; i++){
                    ull ad = dup(aa[i]);
                    #pragma unroll
                    for (int j = 0; j < 4; j++) acc[i][j] = fma2(ad, bp[j], acc[i][j]);
                }
            }
            __syncthreads();
        }
        #pragma unroll
        for (int i = 0; i < 4; i++){
            #pragma unroll
            for (int jp = 0; jp < 4; jp++){
                float2 f = up2(acc[i][jp]);
                int r = (ty*4 + i)*128 + tx*8 + 2*jp;
                sm[OFF_XXX + r]   = tanhf(f.x);
                sm[OFF_XXX + r+1] = tanhf(f.y);
            }
        }
        __syncthreads();
    }

    // ---------------- Phase B ----------------
    float* xxx_s = sm + OFF_XXX;
    float* w2_s  = sm + OFF_W2;
    float* dw1_s = sm + OFF_DW1;
    float* xw_s  = sm + OFF_XW;

    ull acc_d1[4][2];
    #pragma unroll
    for (int i = 0; i < 4; i++){ acc_d1[i][0] = 0ull; acc_d1[i][1] = 0ull; }

    for (int c0 = 0; c0 < CC; c0 += 128){
        #pragma unroll
        for (int l = 0; l < 64; l++){
            int i = tid + l*256;
            w2_s[i] = w2[(size_t)(i >> 7)*CC + c0 + (i & 127)];
        }
        #pragma unroll
        for (int l = 0; l < 32; l++){
            int i = tid + l*256;
            int kk = i >> 6, j = i & 63;
            dw1_s[kk*68 + j] = dw1[(size_t)(c0+kk)*64 + j];
        }
        __syncthreads();

        #pragma unroll
        for (int it = 0; it < 4; it++){
            const int tl  = ty*4 + it;
            const int tok = bt0 + tl;
            ull m2[4][4];
            #pragma unroll
            for (int f = 0; f < 4; f++)
                #pragma unroll
                for (int j = 0; j < 4; j++) m2[f][j] = 0ull;

            #pragma unroll
            for (int kk = 0; kk < 32; kk++){
                #pragma unroll
                for (int f = 0; f < 4; f++){
                    ull ad = dup(xxx_s[tl*128 + f*32 + kk]);
                    ulonglong2 wa = *(const ulonglong2*)&w2_s[(f*32+kk)*128 + tx*8];
                    ulonglong2 wb = *(const ulonglong2*)&w2_s[(f*32+kk)*128 + tx*8 + 4];
                    m2[f][0] = fma2(ad, wa.x, m2[f][0]);
                    m2[f][1] = fma2(ad, wa.y, m2[f][1]);
                    m2[f][2] = fma2(ad, wb.x, m2[f][2]);
                    m2[f][3] = fma2(ad, wb.y, m2[f][3]);
                }
            }
            // epilogue
            const int cb = c0 + tx*8;
            const size_t gofs = (size_t)tok*CC + cb;
            float4 xa = *(const float4*)&hidden[gofs];
            float4 xb = *(const float4*)&hidden[gofs + 4];
            const float* prow = ((tok & (TT-1)) == 0) ? (attn_x + (size_t)(tok >> 12)*CC)
                                                      : (hidden + (size_t)(tok-1)*CC);
            float4 pa = *(const float4*)&prow[cb];
            float4 pb = *(const float4*)&prow[cb + 4];
            float xv[8] = {xa.x,xa.y,xa.z,xa.w,xb.x,xb.y,xb.z,xb.w};
            float pv[8] = {pa.x,pa.y,pa.z,pa.w,pb.x,pb.y,pb.z,pb.w};
            float xd[8];
            #pragma unroll
            for (int e = 0; e < 8; e++) xd[e] = pv[e] - xv[e];

            const int hh = cb >> 6, lmm = cb & 63;
            const size_t sb = ((size_t)tok*32 + hh)*256 + lmm;
            const float* maas[4] = {maa_w, maa_k, maa_v, maa_r};
            const int seq_slot[4] = {-1, 1, 3, 0};   // f=0 (xw) -> smem
            #pragma unroll
            for (int f = 0; f < 4; f++){
                float4 ma = *(const float4*)&maas[f][cb];
                float4 mb = *(const float4*)&maas[f][cb + 4];
                float mm[8] = {ma.x,ma.y,ma.z,ma.w,mb.x,mb.y,mb.z,mb.w};
                float mq[8];
                #pragma unroll
                for (int jp = 0; jp < 4; jp++){
                    float2 qv = up2(m2[f][jp]);
                    mq[2*jp] = qv.x; mq[2*jp+1] = qv.y;
                }
                float o[8];
                #pragma unroll
                for (int e = 0; e < 8; e++) o[e] = xv[e] + xd[e]*(mm[e] + mq[e]);
                if (f == 0){
                    *(float4*)&xw_s[tl*132 + tx*8]     = make_float4(o[0],o[1],o[2],o[3]);
                    *(float4*)&xw_s[tl*132 + tx*8 + 4] = make_float4(o[4],o[5],o[6],o[7]);
                } else {
                    float* dst = &g_seq[sb + seq_slot[f]*64];
                    *(float4*)&dst[0] = make_float4(o[0],o[1],o[2],o[3]);
                    *(float4*)&dst[4] = make_float4(o[4],o[5],o[6],o[7]);
                }
            }
        }
        __syncthreads();

        // accumulate d1 += xw_chunk @ dw1_chunk   (out 64 tok x 64 j)
        #pragma unroll 4
        for (int kk = 0; kk < 128; kk++){
            ulonglong2 bp = *(const ulonglong2*)&dw1_s[kk*68 + tx*4];
            #pragma unroll
            for (int i = 0; i < 4; i++){
                ull ad = dup(xw_s[(ty*4+i)*132 + kk]);
                acc_d1[i][0] = fma2(ad, bp.x, acc_d1[i][0]);
                acc_d1[i][1] = fma2(ad, bp.y, acc_d1[i][1]);
            }
        }
        __syncthreads();
    }

    // ---------------- Phase C: decay output ----------------
    float* d1_s  = sm + OFF_D1;
    float* dw2_s = sm + OFF_DW2;
    #pragma unroll
    for (int i = 0; i < 4; i++){
        float2 e0 = up2(acc_d1[i][0]);
        float2 e1 = up2(acc_d1[i][1]);
        int r = (ty*4 + i)*68 + tx*4;
        d1_s[r]   = tanhf(e0.x);
        d1_s[r+1] = tanhf(e0.y);
        d1_s[r+2] = tanhf(e1.x);
        d1_s[r+3] = tanhf(e1.y);
    }
    __syncthreads();

    for (int c0 = 0; c0 < CC; c0 += 128){
        #pragma unroll
        for (int l = 0; l < 32; l++){
            int i = tid + l*256;
            dw2_s[i] = dw2[(size_t)(i >> 7)*CC + c0 + (i & 127)];
        }
        __syncthreads();
        #pragma unroll
        for (int it = 0; it < 4; it++){
            const int tl  = ty*4 + it;
            const int tok = bt0 + tl;
            ull a2[4];
            #pragma unroll
            for (int j = 0; j < 4; j++) a2[j] = 0ull;
            #pragma unroll
            for (int jj = 0; jj < 64; jj++){
                ull ad = dup(d1_s[tl*68 + jj]);
                ulonglong2 wa = *(const ulonglong2*)&dw2_s[jj*128 + tx*8];
                ulonglong2 wb = *(const ulonglong2*)&dw2_s[jj*128 + tx*8 + 4];
                a2[0] = fma2(ad, wa.x, a2[0]);
                a2[1] = fma2(ad, wa.y, a2[1]);
                a2[2] = fma2(ad, wb.x, a2[2]);
                a2[3] = fma2(ad, wb.y, a2[3]);
            }
            const int cb = c0 + tx*8;
            float4 t0 = *(const float4*)&tdecay[cb];
            float4 t1 = *(const float4*)&tdecay[cb + 4];
            float td[8] = {t0.x,t0.y,t0.z,t0.w,t1.x,t1.y,t1.z,t1.w};
            float mq[8];
            #pragma unroll
            for (int jp = 0; jp < 4; jp++){
                float2 qv = up2(a2[jp]);
                mq[2*jp] = qv.x; mq[2*jp+1] = qv.y;
            }
            float o[8];
            #pragma unroll
            for (int e = 0; e < 8; e++) o[e] = expf(-expf(td[e] + mq[e]));
            const int hh = cb >> 6, lmm = cb & 63;
            float* dst = &g_seq[((size_t)tok*32 + hh)*256 + 128 + lmm];
            *(float4*)&dst[0] = make_float4(o[0],o[1],o[2],o[3]);
            *(float4*)&dst[4] = make_float4(o[4],o[5],o[6],o[7]);
        }
        __syncthreads();
    }
}

// =====================================================================
// k_scan: WKV scan. 128 blocks = (b, h, m-half). 256 threads:
//   lm = tid&31 (m within half), q = tid>>5 (n-octet). 4 f32x2 state
//   pairs per thread. cp.async ring: 32 steps (4 groups of 8).
// =====================================================================
__global__ __launch_bounds__(256) void k_scan(
    const float* __restrict__ attn_kv, const float* __restrict__ faaaa,
    float* __restrict__ out)
{
    __shared__ float ring[32*256];     // 32KB
    __shared__ float partial[8][264];

    const int tid = threadIdx.x;
    const int bid = blockIdx.x;
    const int b = bid >> 6, h = (bid >> 1) & 31, half = bid & 1;
    const int lm = tid & 31, q = tid >> 5;
    const int mg = half*32 + lm;

    const ull ud = dup(faaaa[h]);

    ull s2[4];
    const float* kvp = attn_kv + ((size_t)(b*32 + h))*4096;
    #pragma unroll
    for (int j = 0; j < 4; j++){
        int n0 = q*8 + 2*j;
        s2[j] = pk(kvp[n0*64 + mg], kvp[(n0+1)*64 + mg]);
    }

    const float4* srcb = (const float4*)g_seq + ((size_t)b*TT)*2048 + h*64;
    const uint32_t rbase = (uint32_t)__cvta_generic_to_shared(ring);
    const int e0 = tid*2, e1 = tid*2 + 1;    // 0..511 (8 steps x 64 float4)
    const int s0 = e0 >> 6, o0 = e0 & 63;
    const int s1 = e1 >> 6, o1 = e1 & 63;

    // prologue: groups 0..2
    #pragma unroll
    for (int gg = 0; gg < 3; gg++){
        int t0 = gg*8;
        int ta = t0 + s0, tb = t0 + s1;
        cpa16(rbase + (uint32_t)((ta & 31)*1024 + o0*16), srcb + (size_t)ta*2048 + o0);
        cpa16(rbase + (uint32_t)((tb & 31)*1024 + o1*16), srcb + (size_t)tb*2048 + o1);
        cpa_commit();
    }

    const size_t obase = (size_t)b*TT*CC + h*64 + half*32;
    const int nb = q*8;

    for (int g = 0; g < TT/8; g++){
        asm volatile("cp.async.wait_group 2;\n" ::: "memory");
        __syncthreads();
        #pragma unroll
        for (int ti = 0; ti < 8; ti++){
            const float* st = &ring[(((g << 3) + ti) & 31) << 8];
            const ull vd = dup(st[192 + mg]);
            ulonglong2 ra = *(const ulonglong2*)&st[nb];
            ulonglong2 rb = *(const ulonglong2*)&st[nb + 4];
            ulonglong2 ka = *(const ulonglong2*)&st[64 + nb];
            ulonglong2 kb = *(const ulonglong2*)&st[64 + nb + 4];
            ulonglong2 wa = *(const ulonglong2*)&st[128 + nb];
            ulonglong2 wb = *(const ulonglong2*)&st[128 + nb + 4];
            ull r2[4]  = {ra.x, ra.y, rb.x, rb.y};
            ull k2[4]  = {ka.x, ka.y, kb.x, kb.y};
            ull w2v[4] = {wa.x, wa.y, wb.x, wb.y};
            ull y0 = 0ull, y1 = 0ull;
            #pragma unroll
            for (int j = 0; j < 4; j++){
                ull a2 = mul2(k2[j], vd);
                ull t2 = fma2(ud, a2, s2[j]);
                if (j & 1) y1 = fma2(r2[j], t2, y1);
                else       y0 = fma2(r2[j], t2, y0);
                s2[j] = fma2(w2v[j], s2[j], a2);
            }
            float2 f0 = up2(y0), f1 = up2(y1);
            partial[ti][q*33 + lm] = (f0.x + f0.y) + (f1.x + f1.y);
        }
        __syncthreads();
        // reduce across the 8 n-octets; thread tid -> step (tid>>5), m=lm
        {
            const int s = tid >> 5;
            float y = 0.f;
            #pragma unroll
            for (int q2 = 0; q2 < 8; q2++) y += partial[s][q2*33 + lm];
            out[obase + (size_t)((g << 3) + s)*CC + lm] = y;
        }
        // issue group g+3
        if (g + 3 < TT/8){
            int t0 = (g + 3)*8;
            int ta = t0 + s0, tb = t0 + s1;
            cpa16(rbase + (uint32_t)((ta & 31)*1024 + o0*16), srcb + (size_t)ta*2048 + o0);
            cpa16(rbase + (uint32_t)((tb & 31)*1024 + o1*16), srcb + (size_t)tb*2048 + o1);
        }
        cpa_commit();
    }
}

// =====================================================================
extern "C" void kernel_launch(void* const* d_in, const int* in_sizes, int n_in,
                              void* d_out, int out_size) {
    const float* hidden  = (const float*)d_in[0];
    const float* attn_x  = (const float*)d_in[1];
    const float* attn_kv = (const float*)d_in[2];
    // d_in[3] = ffn_x (unused)
    const float* maa_x   = (const float*)d_in[4];
    const float* maa_w   = (const float*)d_in[5];
    const float* maa_k   = (const float*)d_in[6];
    const float* maa_v   = (const float*)d_in[7];
    const float* maa_r   = (const float*)d_in[8];
    // d_in[9] = time_maa_g (unused)
    const float* w1      = (const float*)d_in[10];
    const float* w2      = (const float*)d_in[11];
    const float* tdecay  = (const float*)d_in[12];
    const float* dw1     = (const float*)d_in[13];
    const float* dw2     = (const float*)d_in[14];
    const float* faaaa   = (const float*)d_in[15];
    float* out = (float*)d_out;

    static bool attr_set = false;
    if (!attr_set){
        cudaFuncSetAttribute(k_fused, cudaFuncAttributeMaxDynamicSharedMemorySize, SMEM_FUSED_BYTES);
        attr_set = true;
    }

    k_fused<<<NT/64, 256, SMEM_FUSED_BYTES>>>(hidden, attn_x, maa_x, maa_w, maa_k,
                                              maa_v, maa_r, w1, w2, dw1, dw2, tdecay);
    k_scan <<<128, 256>>>(attn_kv, faaaa, out);
}

// round 4
// speedup vs baseline: 2.9293x; 2.2659x over previous
#include <cuda_runtime.h>
#include <cstdint>

#define BB 2
#define TT 4096
#define CC 2048
#define NT (BB*TT)   // 8192 tokens

typedef unsigned long long ull;

// interleaved scan input: [tok][h][f][64], f: 0=r, 1=k, 2=wd, 3=v  (256MB)
__device__ float g_seq[(size_t)NT*32*4*64];

// ---------------- packed f32x2 helpers ----------------
__device__ __forceinline__ ull pk(float lo, float hi){
    ull r; asm("mov.b64 %0,{%1,%2};" : "=l"(r) : "f"(lo), "f"(hi)); return r;
}
__device__ __forceinline__ ull dup(float x){
    ull r; asm("mov.b64 %0,{%1,%1};" : "=l"(r) : "f"(x)); return r;
}
__device__ __forceinline__ float2 up2(ull a){
    float2 f; asm("mov.b64 {%0,%1},%2;" : "=f"(f.x), "=f"(f.y) : "l"(a)); return f;
}
__device__ __forceinline__ ull fma2(ull a, ull b, ull c){
    ull d; asm("fma.rn.f32x2 %0,%1,%2,%3;" : "=l"(d) : "l"(a), "l"(b), "l"(c)); return d;
}
__device__ __forceinline__ ull mul2(ull a, ull b){
    ull d; asm("mul.rn.f32x2 %0,%1,%2;" : "=l"(d) : "l"(a), "l"(b)); return d;
}
__device__ __forceinline__ void cpa16(uint32_t dst, const void* src){
    asm volatile("cp.async.cg.shared.global [%0],[%1],16;\n" :: "r"(dst), "l"(src) : "memory");
}
__device__ __forceinline__ void cpa_commit(){
    asm volatile("cp.async.commit_group;\n" ::: "memory");
}

// ---------------- k_fused shared-memory layout (float offsets) ----------------
#define OFF_XXX 0            // [64][128]    8192   (persistent through phase B)
#define OFF_A   8192         // [32][68]     2176   (phase A)
#define OFF_B   10368        // [32][128]    4096   (phase A)
#define OFF_XS  8192         // [64][132]    8448   (phase B)
#define OFF_XDS 16640        // [64][132]    8448   (phase B)
#define OFF_XW  25088        // [64][132]    8448   (phase B)
#define OFF_DW1 33536        // [128][68]    8704   (phase B)
#define OFF_W2F 42240        // [32][128]    4096   (phase B) -> end 46336
#define OFF_D1  8192         // [64][68]     4352   (phase C)
#define OFF_DW2 12544        // [64][128]    8192   (phase C)
#define SMEM_F 46336
#define SMEM_BYTES (SMEM_F*4)

// =====================================================================
// k_fused: token-shift mix + decay LoRA. 64 tokens/block, 256 threads,
// grid 128. tx = tid&15 (8 output cols), ty = tid>>4 (4 tokens).
// =====================================================================
__global__ __launch_bounds__(256, 1) void k_fused(
    const float* __restrict__ hidden, const float* __restrict__ attn_x,
    const float* __restrict__ maa_x,  const float* __restrict__ maa_w,
    const float* __restrict__ maa_k,  const float* __restrict__ maa_v,
    const float* __restrict__ maa_r,  const float* __restrict__ w1,
    const float* __restrict__ w2,     const float* __restrict__ dw1,
    const float* __restrict__ dw2,    const float* __restrict__ tdecay)
{
    extern __shared__ float sm[];
    const int tid = threadIdx.x;
    const int tx = tid & 15, ty = tid >> 4;
    const int bt0 = blockIdx.x * 64;

    // ================= Phase A: xxx = tanh(z @ W1[:,:128]) =================
    {
        float* As = sm + OFF_A;
        float* Bs = sm + OFF_B;
        float rx[8], rp[8], rm[8], rb[16];

        auto prefA = [&](int kc){
            #pragma unroll
            for (int l = 0; l < 8; l++){
                int i = tid + l*256; int kk = i & 31, tl = i >> 5;
                int tok = bt0 + tl; int c = kc + kk;
                rx[l] = hidden[(size_t)tok*CC + c];
                rp[l] = ((tok & (TT-1)) == 0) ? attn_x[(size_t)(tok >> 12)*CC + c]
                                              : hidden[(size_t)(tok-1)*CC + c];
                rm[l] = maa_x[c];
            }
            #pragma unroll
            for (int l = 0; l < 16; l++){
                int i = tid + l*256; int kk = i >> 7, n = i & 127;
                rb[l] = w1[(size_t)(kc+kk)*160 + n];
            }
        };

        ull acc[4][4];
        #pragma unroll
        for (int i = 0; i < 4; i++)
            #pragma unroll
            for (int j = 0; j < 4; j++) acc[i][j] = 0ull;

        prefA(0);
        for (int kc = 0; kc < CC; kc += 32){
            #pragma unroll
            for (int l = 0; l < 8; l++){
                int i = tid + l*256; int kk = i & 31, tl = i >> 5;
                As[kk*68 + tl] = rx[l] + (rp[l] - rx[l])*rm[l];
            }
            #pragma unroll
            for (int l = 0; l < 16; l++){
                int i = tid + l*256; int kk = i >> 7, n = i & 127;
                Bs[kk*128 + n] = rb[l];
            }
            __syncthreads();
            if (kc + 32 < CC) prefA(kc + 32);   // LDGs fly under compute
            #pragma unroll
            for (int kk = 0; kk < 32; kk++){
                float4 av = *(const float4*)&As[kk*68 + ty*4];
                ulonglong2 b01 = *(const ulonglong2*)&Bs[kk*128 + tx*8];
                ulonglong2 b23 = *(const ulonglong2*)&Bs[kk*128 + tx*8 + 4];
                ull bp[4] = {b01.x, b01.y, b23.x, b23.y};
                float aa[4] = {av.x, av.y, av.z, av.w};
                #pragma unroll
                for (int i = 0; i < 4; i++){
                    ull ad = dup(aa[i]);
                    #pragma unroll
                    for (int j = 0; j < 4; j++) acc[i][j] = fma2(ad, bp[j], acc[i][j]);
                }
            }
            __syncthreads();
        }
        #pragma unroll
        for (int i = 0; i < 4; i++){
            #pragma unroll
            for (int jp = 0; jp < 4; jp++){
                float2 f = up2(acc[i][jp]);
                int r = (ty*4 + i)*128 + tx*8 + 2*jp;
                sm[OFF_XXX + r]   = tanhf(f.x);
                sm[OFF_XXX + r+1] = tanhf(f.y);
            }
        }
        __syncthreads();
    }

    // ================= Phase B: per-128-col chunk =================
    float* xxx_s = sm + OFF_XXX;
    float* xs    = sm + OFF_XS;
    float* xds   = sm + OFF_XDS;
    float* xw_s  = sm + OFF_XW;
    float* dw1_s = sm + OFF_DW1;
    float* w2f   = sm + OFF_W2F;

    ull acc_d1[4][2];
    #pragma unroll
    for (int i = 0; i < 4; i++){ acc_d1[i][0] = 0ull; acc_d1[i][1] = 0ull; }

    for (int c0 = 0; c0 < CC; c0 += 128){
        // stage x and (prev - x) slices
        #pragma unroll
        for (int l = 0; l < 32; l++){
            int i = tid + l*256; int tl = i >> 7, n = i & 127;
            int tok = bt0 + tl; int c = c0 + n;
            float x = hidden[(size_t)tok*CC + c];
            float p = ((tok & (TT-1)) == 0) ? attn_x[(size_t)(tok >> 12)*CC + c]
                                            : hidden[(size_t)(tok-1)*CC + c];
            xs [tl*132 + n] = x;
            xds[tl*132 + n] = p - x;
        }
        // stage dw1 chunk rows
        #pragma unroll
        for (int l = 0; l < 32; l++){
            int i = tid + l*256; int kk = i >> 6, j = i & 63;
            dw1_s[kk*68 + j] = dw1[(size_t)(c0+kk)*64 + j];
        }

        const int cb = c0 + tx*8;
        const int hh = cb >> 6, lmm = cb & 63;

        #pragma unroll
        for (int f = 0; f < 4; f++){
            __syncthreads();   // previous readers of w2f done
            #pragma unroll
            for (int l = 0; l < 16; l++){
                int i = tid + l*256; int kk = i >> 7, n = i & 127;
                w2f[kk*128 + n] = w2[((size_t)f*32 + kk)*CC + c0 + n];
            }
            __syncthreads();

            ull macc[4][4];
            #pragma unroll
            for (int i = 0; i < 4; i++)
                #pragma unroll
                for (int j = 0; j < 4; j++) macc[i][j] = 0ull;

            #pragma unroll
            for (int kk = 0; kk < 32; kk++){
                ulonglong2 wa = *(const ulonglong2*)&w2f[kk*128 + tx*8];
                ulonglong2 wb = *(const ulonglong2*)&w2f[kk*128 + tx*8 + 4];
                ull bp[4] = {wa.x, wa.y, wb.x, wb.y};
                #pragma unroll
                for (int i = 0; i < 4; i++){
                    ull ad = dup(xxx_s[(ty*4 + i)*128 + f*32 + kk]);
                    #pragma unroll
                    for (int j = 0; j < 4; j++) macc[i][j] = fma2(ad, bp[j], macc[i][j]);
                }
            }
            // epilogue for this f
            const float* maaf = (f==0) ? maa_w : (f==1) ? maa_k : (f==2) ? maa_v : maa_r;
            float4 ma = *(const float4*)&maaf[cb];
            float4 mb = *(const float4*)&maaf[cb + 4];
            float mmv[8] = {ma.x,ma.y,ma.z,ma.w,mb.x,mb.y,mb.z,mb.w};
            const int slot = (f==1) ? 1 : (f==2) ? 3 : 0;   // f==3 -> r slot 0
            #pragma unroll
            for (int i = 0; i < 4; i++){
                const int tl = ty*4 + i;
                float4 xa = *(const float4*)&xs [tl*132 + tx*8];
                float4 xb = *(const float4*)&xs [tl*132 + tx*8 + 4];
                float4 da = *(const float4*)&xds[tl*132 + tx*8];
                float4 db = *(const float4*)&xds[tl*132 + tx*8 + 4];
                float xv[8] = {xa.x,xa.y,xa.z,xa.w,xb.x,xb.y,xb.z,xb.w};
                float dv[8] = {da.x,da.y,da.z,da.w,db.x,db.y,db.z,db.w};
                float mq[8];
                #pragma unroll
                for (int jp = 0; jp < 4; jp++){
                    float2 q = up2(macc[i][jp]);
                    mq[2*jp] = q.x; mq[2*jp+1] = q.y;
                }
                float o[8];
                #pragma unroll
                for (int e = 0; e < 8; e++) o[e] = xv[e] + dv[e]*(mmv[e] + mq[e]);
                if (f == 0){
                    *(float4*)&xw_s[tl*132 + tx*8]     = make_float4(o[0],o[1],o[2],o[3]);
                    *(float4*)&xw_s[tl*132 + tx*8 + 4] = make_float4(o[4],o[5],o[6],o[7]);
                } else {
                    float* dst = &g_seq[((size_t)(bt0 + tl)*32 + hh)*256 + slot*64 + lmm];
                    *(float4*)&dst[0] = make_float4(o[0],o[1],o[2],o[3]);
                    *(float4*)&dst[4] = make_float4(o[4],o[5],o[6],o[7]);
                }
            }
        }
        __syncthreads();   // xw_s complete before d1 accumulate

        // d1 += xw_chunk @ dw1_chunk  (per thread: 4 tokens x 4 j-cols)
        #pragma unroll 2
        for (int kk = 0; kk < 128; kk++){
            ulonglong2 bp = *(const ulonglong2*)&dw1_s[kk*68 + tx*4];
            #pragma unroll
            for (int i = 0; i < 4; i++){
                ull ad = dup(xw_s[(ty*4 + i)*132 + kk]);
                acc_d1[i][0] = fma2(ad, bp.x, acc_d1[i][0]);
                acc_d1[i][1] = fma2(ad, bp.y, acc_d1[i][1]);
            }
        }
        __syncthreads();   // region reuse next chunk
    }

    // ================= Phase C: wd = exp(-exp(td + tanh(d1) @ dw2)) =================
    float* d1_s  = sm + OFF_D1;
    float* dw2_s = sm + OFF_DW2;
    #pragma unroll
    for (int i = 0; i < 4; i++){
        float2 e0 = up2(acc_d1[i][0]);
        float2 e1 = up2(acc_d1[i][1]);
        int r = (ty*4 + i)*68 + tx*4;
        d1_s[r]   = tanhf(e0.x);
        d1_s[r+1] = tanhf(e0.y);
        d1_s[r+2] = tanhf(e1.x);
        d1_s[r+3] = tanhf(e1.y);
    }
    __syncthreads();

    for (int c0 = 0; c0 < CC; c0 += 128){
        #pragma unroll
        for (int l = 0; l < 32; l++){
            int i = tid + l*256;
            dw2_s[i] = dw2[(size_t)(i >> 7)*CC + c0 + (i & 127)];
        }
        __syncthreads();
        ull wacc[4][4];
        #pragma unroll
        for (int i = 0; i < 4; i++)
            #pragma unroll
            for (int j = 0; j < 4; j++) wacc[i][j] = 0ull;
        #pragma unroll 4
        for (int jj = 0; jj < 64; jj++){
            ulonglong2 wa = *(const ulonglong2*)&dw2_s[jj*128 + tx*8];
            ulonglong2 wb = *(const ulonglong2*)&dw2_s[jj*128 + tx*8 + 4];
            #pragma unroll
            for (int i = 0; i < 4; i++){
                ull ad = dup(d1_s[(ty*4 + i)*68 + jj]);
                wacc[i][0] = fma2(ad, wa.x, wacc[i][0]);
                wacc[i][1] = fma2(ad, wa.y, wacc[i][1]);
                wacc[i][2] = fma2(ad, wb.x, wacc[i][2]);
                wacc[i][3] = fma2(ad, wb.y, wacc[i][3]);
            }
        }
        const int cb = c0 + tx*8;
        const int hh = cb >> 6, lmm = cb & 63;
        float4 t0 = *(const float4*)&tdecay[cb];
        float4 t1 = *(const float4*)&tdecay[cb + 4];
        float td[8] = {t0.x,t0.y,t0.z,t0.w,t1.x,t1.y,t1.z,t1.w};
        #pragma unroll
        for (int i = 0; i < 4; i++){
            const int tl = ty*4 + i;
            float mq[8];
            #pragma unroll
            for (int jp = 0; jp < 4; jp++){
                float2 q = up2(wacc[i][jp]);
                mq[2*jp] = q.x; mq[2*jp+1] = q.y;
            }
            float o[8];
            #pragma unroll
            for (int e = 0; e < 8; e++) o[e] = expf(-expf(td[e] + mq[e]));
            float* dst = &g_seq[((size_t)(bt0 + tl)*32 + hh)*256 + 128 + lmm];
            *(float4*)&dst[0] = make_float4(o[0],o[1],o[2],o[3]);
            *(float4*)&dst[4] = make_float4(o[4],o[5],o[6],o[7]);
        }
        __syncthreads();
    }
}

// =====================================================================
// k_scan: unchanged from R3 (366us). 128 blocks = (b, h, m-half).
// =====================================================================
__global__ __launch_bounds__(256) void k_scan(
    const float* __restrict__ attn_kv, const float* __restrict__ faaaa,
    float* __restrict__ out)
{
    __shared__ float ring[32*256];
    __shared__ float partial[8][264];

    const int tid = threadIdx.x;
    const int bid = blockIdx.x;
    const int b = bid >> 6, h = (bid >> 1) & 31, half = bid & 1;
    const int lm = tid & 31, q = tid >> 5;
    const int mg = half*32 + lm;

    const ull ud = dup(faaaa[h]);

    ull s2[4];
    const float* kvp = attn_kv + ((size_t)(b*32 + h))*4096;
    #pragma unroll
    for (int j = 0; j < 4; j++){
        int n0 = q*8 + 2*j;
        s2[j] = pk(kvp[n0*64 + mg], kvp[(n0+1)*64 + mg]);
    }

    const float4* srcb = (const float4*)g_seq + ((size_t)b*TT)*2048 + h*64;
    const uint32_t rbase = (uint32_t)__cvta_generic_to_shared(ring);
    const int e0 = tid*2, e1 = tid*2 + 1;
    const int s0 = e0 >> 6, o0 = e0 & 63;
    const int s1 = e1 >> 6, o1 = e1 & 63;

    #pragma unroll
    for (int gg = 0; gg < 3; gg++){
        int t0 = gg*8;
        int ta = t0 + s0, tb = t0 + s1;
        cpa16(rbase + (uint32_t)((ta & 31)*1024 + o0*16), srcb + (size_t)ta*2048 + o0);
        cpa16(rbase + (uint32_t)((tb & 31)*1024 + o1*16), srcb + (size_t)tb*2048 + o1);
        cpa_commit();
    }

    const size_t obase = (size_t)b*TT*CC + h*64 + half*32;
    const int nb = q*8;

    for (int g = 0; g < TT/8; g++){
        asm volatile("cp.async.wait_group 2;\n" ::: "memory");
        __syncthreads();
        #pragma unroll
        for (int ti = 0; ti < 8; ti++){
            const float* st = &ring[(((g << 3) + ti) & 31) << 8];
            const ull vd = dup(st[192 + mg]);
            ulonglong2 ra = *(const ulonglong2*)&st[nb];
            ulonglong2 rb = *(const ulonglong2*)&st[nb + 4];
            ulonglong2 ka = *(const ulonglong2*)&st[64 + nb];
            ulonglong2 kb = *(const ulonglong2*)&st[64 + nb + 4];
            ulonglong2 wa = *(const ulonglong2*)&st[128 + nb];
            ulonglong2 wb = *(const ulonglong2*)&st[128 + nb + 4];
            ull r2[4]  = {ra.x, ra.y, rb.x, rb.y};
            ull k2[4]  = {ka.x, ka.y, kb.x, kb.y};
            ull w2v[4] = {wa.x, wa.y, wb.x, wb.y};
            ull y0 = 0ull, y1 = 0ull;
            #pragma unroll
            for (int j = 0; j < 4; j++){
                ull a2 = mul2(k2[j], vd);
                ull t2 = fma2(ud, a2, s2[j]);
                if (j & 1) y1 = fma2(r2[j], t2, y1);
                else       y0 = fma2(r2[j], t2, y0);
                s2[j] = fma2(w2v[j], s2[j], a2);
            }
            float2 f0 = up2(y0), f1 = up2(y1);
            partial[ti][q*33 + lm] = (f0.x + f0.y) + (f1.x + f1.y);
        }
        __syncthreads();
        {
            const int s = tid >> 5;
            float y = 0.f;
            #pragma unroll
            for (int q2 = 0; q2 < 8; q2++) y += partial[s][q2*33 + lm];
            out[obase + (size_t)((g << 3) + s)*CC + lm] = y;
        }
        if (g + 3 < TT/8){
            int t0 = (g + 3)*8;
            int ta = t0 + s0, tb = t0 + s1;
            cpa16(rbase + (uint32_t)((ta & 31)*1024 + o0*16), srcb + (size_t)ta*2048 + o0);
            cpa16(rbase + (uint32_t)((tb & 31)*1024 + o1*16), srcb + (size_t)tb*2048 + o1);
        }
        cpa_commit();
    }
}

// =====================================================================
extern "C" void kernel_launch(void* const* d_in, const int* in_sizes, int n_in,
                              void* d_out, int out_size) {
    const float* hidden  = (const float*)d_in[0];
    const float* attn_x  = (const float*)d_in[1];
    const float* attn_kv = (const float*)d_in[2];
    const float* maa_x   = (const float*)d_in[4];
    const float* maa_w   = (const float*)d_in[5];
    const float* maa_k   = (const float*)d_in[6];
    const float* maa_v   = (const float*)d_in[7];
    const float* maa_r   = (const float*)d_in[8];
    const float* w1      = (const float*)d_in[10];
    const float* w2      = (const float*)d_in[11];
    const float* tdecay  = (const float*)d_in[12];
    const float* dw1     = (const float*)d_in[13];
    const float* dw2     = (const float*)d_in[14];
    const float* faaaa   = (const float*)d_in[15];
    float* out = (float*)d_out;

    static bool attr_set = false;
    if (!attr_set){
        cudaFuncSetAttribute(k_fused, cudaFuncAttributeMaxDynamicSharedMemorySize, SMEM_BYTES);
        attr_set = true;
    }

    k_fused<<<NT/64, 256, SMEM_BYTES>>>(hidden, attn_x, maa_x, maa_w, maa_k,
                                        maa_v, maa_r, w1, w2, dw1, dw2, tdecay);
    k_scan <<<128, 256>>>(attn_kv, faaaa, out);
}

// round 5
// speedup vs baseline: 3.1478x; 1.0746x over previous
#include <cuda_runtime.h>
#include <cstdint>

#define BB 2
#define TT 4096
#define CC 2048
#define NT (BB*TT)   // 8192 tokens

typedef unsigned long long ull;

// interleaved scan input: [tok][h][f][64], f: 0=r, 1=k, 2=wd, 3=v  (256MB)
__device__ float g_seq[(size_t)NT*32*4*64];

// ---------------- packed f32x2 helpers ----------------
__device__ __forceinline__ ull pk(float lo, float hi){
    ull r; asm("mov.b64 %0,{%1,%2};" : "=l"(r) : "f"(lo), "f"(hi)); return r;
}
__device__ __forceinline__ ull dup(float x){
    ull r; asm("mov.b64 %0,{%1,%1};" : "=l"(r) : "f"(x)); return r;
}
__device__ __forceinline__ float2 up2(ull a){
    float2 f; asm("mov.b64 {%0,%1},%2;" : "=f"(f.x), "=f"(f.y) : "l"(a)); return f;
}
__device__ __forceinline__ ull fma2(ull a, ull b, ull c){
    ull d; asm("fma.rn.f32x2 %0,%1,%2,%3;" : "=l"(d) : "l"(a), "l"(b), "l"(c)); return d;
}
__device__ __forceinline__ ull mul2(ull a, ull b){
    ull d; asm("mul.rn.f32x2 %0,%1,%2;" : "=l"(d) : "l"(a), "l"(b)); return d;
}
__device__ __forceinline__ void cpa16(uint32_t dst, const void* src){
    asm volatile("cp.async.cg.shared.global [%0],[%1],16;\n" :: "r"(dst), "l"(src) : "memory");
}
__device__ __forceinline__ void cpa_commit(){
    asm volatile("cp.async.commit_group;\n" ::: "memory");
}
__device__ __forceinline__ void cpa_wait0(){
    asm volatile("cp.async.wait_group 0;\n" ::: "memory");
}

// ---------------- k_fused shared layout (float offsets) ----------------
#define OFF_XXX 0            // [64][128]     8192
#define OFF_W2  8192         // [128][128]   16384  -> 24576
#define OFF_DW1 24576        // 2 x [128][68] 17408 -> 41984
#define OFF_XW  41984        // [64][132]     8448  -> 50432
#define OFF_A   50432        // [32][68]      2176  -> 52608
#define OFF_B   52608        // [32][128]     4096  -> 56704
// phase C reuse: D1 at 0 ([64][68] 4352), DW2 at 8192 ([64][128] 8192)
#define SMEM_F 56704
#define SMEM_BYTES (SMEM_F*4)

// =====================================================================
// k_fused: token-shift mix + decay LoRA. 64 tokens/block, 256 threads,
// grid 128. tx = tid&15 (8 output cols), ty = tid>>4 (4 tokens).
// =====================================================================
__global__ __launch_bounds__(256, 1) void k_fused(
    const float* __restrict__ hidden, const float* __restrict__ attn_x,
    const float* __restrict__ maa_x,  const float* __restrict__ maa_w,
    const float* __restrict__ maa_k,  const float* __restrict__ maa_v,
    const float* __restrict__ maa_r,  const float* __restrict__ w1,
    const float* __restrict__ w2,     const float* __restrict__ dw1,
    const float* __restrict__ dw2,    const float* __restrict__ tdecay)
{
    extern __shared__ float sm[];
    const int tid = threadIdx.x;
    const int tx = tid & 15, ty = tid >> 4;
    const int bt0 = blockIdx.x * 64;

    const uint32_t smb = (uint32_t)__cvta_generic_to_shared(sm);

    // helper to stage w2 + dw1 chunk via cp.async (one commit group)
    auto stage_wd = [&](int c0, int buf){
        #pragma unroll
        for (int l = 0; l < 16; l++){
            int i = tid + l*256;                // 0..4095 float4s
            int row = i >> 5, c4 = i & 31;
            cpa16(smb + (uint32_t)(OFF_W2 + row*128 + c4*4)*4u,
                  w2 + (size_t)row*CC + c0 + c4*4);
        }
        #pragma unroll
        for (int l = 0; l < 8; l++){
            int i = tid + l*256;                // 0..2047 float4s
            int row = i >> 4, c4 = i & 15;
            cpa16(smb + (uint32_t)(OFF_DW1 + buf*8704 + row*68 + c4*4)*4u,
                  dw1 + (size_t)(c0 + row)*64 + c4*4);
        }
        cpa_commit();
    };

    // prefetch chunk 0 (w2 + dw1) before phase A
    stage_wd(0, 0);

    // ================= Phase A: xxx = tanh(z @ W1[:,:128]) =================
    {
        float* As = sm + OFF_A;
        float* Bs = sm + OFF_B;
        float rx[8], rp[8], rm[8], rb[16];

        auto prefA = [&](int kc){
            #pragma unroll
            for (int l = 0; l < 8; l++){
                int i = tid + l*256; int kk = i & 31, tl = i >> 5;
                int tok = bt0 + tl; int c = kc + kk;
                rx[l] = hidden[(size_t)tok*CC + c];
                rp[l] = ((tok & (TT-1)) == 0) ? attn_x[(size_t)(tok >> 12)*CC + c]
                                              : hidden[(size_t)(tok-1)*CC + c];
                rm[l] = maa_x[c];
            }
            #pragma unroll
            for (int l = 0; l < 16; l++){
                int i = tid + l*256; int kk = i >> 7, n = i & 127;
                rb[l] = w1[(size_t)(kc+kk)*160 + n];
            }
        };

        ull acc[4][4];
        #pragma unroll
        for (int i = 0; i < 4; i++)
            #pragma unroll
            for (int j = 0; j < 4; j++) acc[i][j] = 0ull;

        prefA(0);
        for (int kc = 0; kc < CC; kc += 32){
            #pragma unroll
            for (int l = 0; l < 8; l++){
                int i = tid + l*256; int kk = i & 31, tl = i >> 5;
                As[kk*68 + tl] = rx[l] + (rp[l] - rx[l])*rm[l];
            }
            #pragma unroll
            for (int l = 0; l < 16; l++){
                int i = tid + l*256; int kk = i >> 7, n = i & 127;
                Bs[kk*128 + n] = rb[l];
            }
            __syncthreads();
            if (kc + 32 < CC) prefA(kc + 32);
            #pragma unroll
            for (int kk = 0; kk < 32; kk++){
                float4 av = *(const float4*)&As[kk*68 + ty*4];
                ulonglong2 b01 = *(const ulonglong2*)&Bs[kk*128 + tx*8];
                ulonglong2 b23 = *(const ulonglong2*)&Bs[kk*128 + tx*8 + 4];
                ull bp[4] = {b01.x, b01.y, b23.x, b23.y};
                float aa[4] = {av.x, av.y, av.z, av.w};
                #pragma unroll
                for (int i = 0; i < 4; i++){
                    ull ad = dup(aa[i]);
                    #pragma unroll
                    for (int j = 0; j < 4; j++) acc[i][j] = fma2(ad, bp[j], acc[i][j]);
                }
            }
            __syncthreads();
        }
        #pragma unroll
        for (int i = 0; i < 4; i++){
            #pragma unroll
            for (int jp = 0; jp < 4; jp++){
                float2 f = up2(acc[i][jp]);
                int r = (ty*4 + i)*128 + tx*8 + 2*jp;
                sm[OFF_XXX + r]   = tanhf(f.x);
                sm[OFF_XXX + r+1] = tanhf(f.y);
            }
        }
    }

    // ================= Phase B =================
    float* xxx_s = sm + OFF_XXX;
    float* w2_s  = sm + OFF_W2;
    float* xw_s  = sm + OFF_XW;

    ull acc_d1[4][2];
    #pragma unroll
    for (int i = 0; i < 4; i++){ acc_d1[i][0] = 0ull; acc_d1[i][1] = 0ull; }

    for (int c0 = 0; c0 < CC; c0 += 128){
        const int cbuf = (c0 >> 7) & 1;
        cpa_wait0();
        __syncthreads();           // w2/dw1 chunk ready; also covers xxx after phase A

        const int cb = c0 + tx*8;
        const int hh = cb >> 6, lmm = cb & 63;

        // x / diff operands -> registers (coalesced, issued before mma)
        float xr[4][8], dr[4][8];
        #pragma unroll
        for (int i = 0; i < 4; i++){
            const int tok = bt0 + ty*4 + i;
            const size_t gofs = (size_t)tok*CC + cb;
            float4 xa = *(const float4*)&hidden[gofs];
            float4 xb = *(const float4*)&hidden[gofs + 4];
            const float* prow = ((tok & (TT-1)) == 0) ? (attn_x + (size_t)(tok >> 12)*CC)
                                                      : (hidden + (size_t)(tok-1)*CC);
            float4 pa = *(const float4*)&prow[cb];
            float4 pb = *(const float4*)&prow[cb + 4];
            xr[i][0]=xa.x; xr[i][1]=xa.y; xr[i][2]=xa.z; xr[i][3]=xa.w;
            xr[i][4]=xb.x; xr[i][5]=xb.y; xr[i][6]=xb.z; xr[i][7]=xb.w;
            dr[i][0]=pa.x-xa.x; dr[i][1]=pa.y-xa.y; dr[i][2]=pa.z-xa.z; dr[i][3]=pa.w-xa.w;
            dr[i][4]=pb.x-xb.x; dr[i][5]=pb.y-xb.y; dr[i][6]=pb.z-xb.z; dr[i][7]=pb.w-xb.w;
        }

        #pragma unroll
        for (int f = 0; f < 4; f++){
            ull macc[4][4];
            #pragma unroll
            for (int i = 0; i < 4; i++)
                #pragma unroll
                for (int j = 0; j < 4; j++) macc[i][j] = 0ull;

            #pragma unroll
            for (int kk = 0; kk < 32; kk++){
                ulonglong2 wa = *(const ulonglong2*)&w2_s[(f*32+kk)*128 + tx*8];
                ulonglong2 wb = *(const ulonglong2*)&w2_s[(f*32+kk)*128 + tx*8 + 4];
                ull bp[4] = {wa.x, wa.y, wb.x, wb.y};
                #pragma unroll
                for (int i = 0; i < 4; i++){
                    ull ad = dup(xxx_s[(ty*4 + i)*128 + f*32 + kk]);
                    #pragma unroll
                    for (int j = 0; j < 4; j++) macc[i][j] = fma2(ad, bp[j], macc[i][j]);
                }
            }
            const float* maaf = (f==0) ? maa_w : (f==1) ? maa_k : (f==2) ? maa_v : maa_r;
            float4 ma = *(const float4*)&maaf[cb];
            float4 mb = *(const float4*)&maaf[cb + 4];
            float mmv[8] = {ma.x,ma.y,ma.z,ma.w,mb.x,mb.y,mb.z,mb.w};
            const int slot = (f==1) ? 1 : (f==2) ? 3 : 0;
            #pragma unroll
            for (int i = 0; i < 4; i++){
                const int tl = ty*4 + i;
                float mq[8];
                #pragma unroll
                for (int jp = 0; jp < 4; jp++){
                    float2 q = up2(macc[i][jp]);
                    mq[2*jp] = q.x; mq[2*jp+1] = q.y;
                }
                float o[8];
                #pragma unroll
                for (int e = 0; e < 8; e++) o[e] = xr[i][e] + dr[i][e]*(mmv[e] + mq[e]);
                if (f == 0){
                    *(float4*)&xw_s[tl*132 + tx*8]     = make_float4(o[0],o[1],o[2],o[3]);
                    *(float4*)&xw_s[tl*132 + tx*8 + 4] = make_float4(o[4],o[5],o[6],o[7]);
                } else {
                    float* dst = &g_seq[((size_t)(bt0 + tl)*32 + hh)*256 + slot*64 + lmm];
                    *(float4*)&dst[0] = make_float4(o[0],o[1],o[2],o[3]);
                    *(float4*)&dst[4] = make_float4(o[4],o[5],o[6],o[7]);
                }
            }
        }
        __syncthreads();           // xw_s complete; w2/dw1 fully consumed

        // prefetch next chunk while we do the d1 accumulation
        if (c0 + 128 < CC) stage_wd(c0 + 128, cbuf ^ 1);
        else               cpa_commit();

        const float* dw1c = sm + OFF_DW1 + cbuf*8704;
        #pragma unroll 2
        for (int kk = 0; kk < 128; kk++){
            ulonglong2 bp = *(const ulonglong2*)&dw1c[kk*68 + tx*4];
            #pragma unroll
            for (int i = 0; i < 4; i++){
                ull ad = dup(xw_s[(ty*4 + i)*132 + kk]);
                acc_d1[i][0] = fma2(ad, bp.x, acc_d1[i][0]);
                acc_d1[i][1] = fma2(ad, bp.y, acc_d1[i][1]);
            }
        }
    }
    cpa_wait0();
    __syncthreads();

    // ================= Phase C: wd = exp(-exp(td + tanh(d1) @ dw2)) =================
    float* d1_s  = sm;             // [64][68] over OFF_XXX
    float* dw2_s = sm + 8192;      // [64][128] over OFF_W2
    #pragma unroll
    for (int i = 0; i < 4; i++){
        float2 e0 = up2(acc_d1[i][0]);
        float2 e1 = up2(acc_d1[i][1]);
        int r = (ty*4 + i)*68 + tx*4;
        d1_s[r]   = tanhf(e0.x);
        d1_s[r+1] = tanhf(e0.y);
        d1_s[r+2] = tanhf(e1.x);
        d1_s[r+3] = tanhf(e1.y);
    }
    __syncthreads();

    for (int c0 = 0; c0 < CC; c0 += 128){
        #pragma unroll
        for (int l = 0; l < 32; l++){
            int i = tid + l*256;
            dw2_s[i] = dw2[(size_t)(i >> 7)*CC + c0 + (i & 127)];
        }
        __syncthreads();
        ull wacc[4][4];
        #pragma unroll
        for (int i = 0; i < 4; i++)
            #pragma unroll
            for (int j = 0; j < 4; j++) wacc[i][j] = 0ull;
        #pragma unroll 4
        for (int jj = 0; jj < 64; jj++){
            ulonglong2 wa = *(const ulonglong2*)&dw2_s[jj*128 + tx*8];
            ulonglong2 wb = *(const ulonglong2*)&dw2_s[jj*128 + tx*8 + 4];
            #pragma unroll
            for (int i = 0; i < 4; i++){
                ull ad = dup(d1_s[(ty*4 + i)*68 + jj]);
                wacc[i][0] = fma2(ad, wa.x, wacc[i][0]);
                wacc[i][1] = fma2(ad, wa.y, wacc[i][1]);
                wacc[i][2] = fma2(ad, wb.x, wacc[i][2]);
                wacc[i][3] = fma2(ad, wb.y, wacc[i][3]);
            }
        }
        const int cb = c0 + tx*8;
        const int hh = cb >> 6, lmm = cb & 63;
        float4 t0 = *(const float4*)&tdecay[cb];
        float4 t1 = *(const float4*)&tdecay[cb + 4];
        float td[8] = {t0.x,t0.y,t0.z,t0.w,t1.x,t1.y,t1.z,t1.w};
        #pragma unroll
        for (int i = 0; i < 4; i++){
            const int tl = ty*4 + i;
            float mq[8];
            #pragma unroll
            for (int jp = 0; jp < 4; jp++){
                float2 q = up2(wacc[i][jp]);
                mq[2*jp] = q.x; mq[2*jp+1] = q.y;
            }
            float o[8];
            #pragma unroll
            for (int e = 0; e < 8; e++) o[e] = expf(-expf(td[e] + mq[e]));
            float* dst = &g_seq[((size_t)(bt0 + tl)*32 + hh)*256 + 128 + lmm];
            *(float4*)&dst[0] = make_float4(o[0],o[1],o[2],o[3]);
            *(float4*)&dst[4] = make_float4(o[4],o[5],o[6],o[7]);
        }
        __syncthreads();
    }
}

// =====================================================================
// k_scan: 128 blocks = (b, h, m-half). 512 threads:
//   lm = tid&31 (m within half), q = tid>>5 (16 n-quartets). 2 f32x2
//   state pairs/thread. cp.async ring 32 steps (4 groups of 8).
// =====================================================================
#define SCAN_SMEM_BYTES ((32*256 + 8*512)*4)   // ring 32KB + partial 16KB

__global__ __launch_bounds__(512) void k_scan(
    const float* __restrict__ attn_kv, const float* __restrict__ faaaa,
    float* __restrict__ out)
{
    extern __shared__ float ssm[];
    float* ring    = ssm;              // [32][256]
    float* partial = ssm + 32*256;     // [8][512]

    const int tid = threadIdx.x;
    const int bid = blockIdx.x;
    const int b = bid >> 6, h = (bid >> 1) & 31, half = bid & 1;
    const int lm = tid & 31, q = tid >> 5;        // q in 0..15
    const int mg = half*32 + lm;

    const ull ud = dup(faaaa[h]);

    ull s2[2];
    const float* kvp = attn_kv + ((size_t)(b*32 + h))*4096;
    #pragma unroll
    for (int j = 0; j < 2; j++){
        int n0 = q*4 + 2*j;
        s2[j] = pk(kvp[n0*64 + mg], kvp[(n0+1)*64 + mg]);
    }

    const float4* srcb = (const float4*)g_seq + ((size_t)b*TT)*2048 + h*64;
    const uint32_t rbase = (uint32_t)__cvta_generic_to_shared(ring);
    const int s0 = tid >> 6, o0 = tid & 63;       // one float4 per thread per group

    #pragma unroll
    for (int gg = 0; gg < 3; gg++){
        int t = gg*8 + s0;
        cpa16(rbase + (uint32_t)((t & 31)*1024 + o0*16), srcb + (size_t)t*2048 + o0);
        cpa_commit();
    }

    const size_t obase = (size_t)b*TT*CC + h*64 + half*32;
    const int nb = q*4;

    for (int g = 0; g < TT/8; g++){
        asm volatile("cp.async.wait_group 2;\n" ::: "memory");
        __syncthreads();
        #pragma unroll
        for (int ti = 0; ti < 8; ti++){
            const float* st = &ring[(((g << 3) + ti) & 31) << 8];
            const ull vd = dup(st[192 + mg]);
            ulonglong2 ra = *(const ulonglong2*)&st[nb];
            ulonglong2 ka = *(const ulonglong2*)&st[64 + nb];
            ulonglong2 wa = *(const ulonglong2*)&st[128 + nb];
            ull r2[2]  = {ra.x, ra.y};
            ull k2[2]  = {ka.x, ka.y};
            ull w2v[2] = {wa.x, wa.y};
            ull y0 = 0ull, y1 = 0ull;
            {
                ull a2 = mul2(k2[0], vd);
                ull t2 = fma2(ud, a2, s2[0]);
                y0 = fma2(r2[0], t2, y0);
                s2[0] = fma2(w2v[0], s2[0], a2);
            }
            {
                ull a2 = mul2(k2[1], vd);
                ull t2 = fma2(ud, a2, s2[1]);
                y1 = fma2(r2[1], t2, y1);
                s2[1] = fma2(w2v[1], s2[1], a2);
            }
            float2 f0 = up2(y0), f1 = up2(y1);
            partial[ti*512 + q*32 + lm] = (f0.x + f0.y) + (f1.x + f1.y);
        }
        __syncthreads();
        if (tid < 256){
            const int s = tid >> 5, lm2 = tid & 31;
            float y = 0.f;
            #pragma unroll
            for (int q2 = 0; q2 < 16; q2++) y += partial[s*512 + q2*32 + lm2];
            out[obase + (size_t)((g << 3) + s)*CC + lm2] = y;
        }
        if (g + 3 < TT/8){
            int t = (g + 3)*8 + s0;
            cpa16(rbase + (uint32_t)((t & 31)*1024 + o0*16), srcb + (size_t)t*2048 + o0);
        }
        cpa_commit();
    }
}

// =====================================================================
extern "C" void kernel_launch(void* const* d_in, const int* in_sizes, int n_in,
                              void* d_out, int out_size) {
    const float* hidden  = (const float*)d_in[0];
    const float* attn_x  = (const float*)d_in[1];
    const float* attn_kv = (const float*)d_in[2];
    const float* maa_x   = (const float*)d_in[4];
    const float* maa_w   = (const float*)d_in[5];
    const float* maa_k   = (const float*)d_in[6];
    const float* maa_v   = (const float*)d_in[7];
    const float* maa_r   = (const float*)d_in[8];
    const float* w1      = (const float*)d_in[10];
    const float* w2      = (const float*)d_in[11];
    const float* tdecay  = (const float*)d_in[12];
    const float* dw1     = (const float*)d_in[13];
    const float* dw2     = (const float*)d_in[14];
    const float* faaaa   = (const float*)d_in[15];
    float* out = (float*)d_out;

    static bool attr_set = false;
    if (!attr_set){
        cudaFuncSetAttribute(k_fused, cudaFuncAttributeMaxDynamicSharedMemorySize, SMEM_BYTES);
        cudaFuncSetAttribute(k_scan,  cudaFuncAttributeMaxDynamicSharedMemorySize, SCAN_SMEM_BYTES);
        attr_set = true;
    }

    k_fused<<<NT/64, 256, SMEM_BYTES>>>(hidden, attn_x, maa_x, maa_w, maa_k,
                                        maa_v, maa_r, w1, w2, dw1, dw2, tdecay);
    k_scan <<<128, 512, SCAN_SMEM_BYTES>>>(attn_kv, faaaa, out);
}